// round 1
// baseline (speedup 1.0000x reference)
#include <cuda_runtime.h>
#include <math.h>

#define N_NODES 50000
#define N_EDGES 800000
#define DDIM    128
#define KDIM    512   /* 4*D : [mean|min|max|std] */
#define NCOLS   384   /* 3*D : W1,W2,W3 output blocks */

#define AVG_DEG_LOG 2.8332133440562162f  /* log(17) */
#define EPS_STD 1e-5f

/* ---------------- scratch (device globals; no cudaMalloc allowed) -------- */
static __device__ int   g_cnt[N_NODES];
static __device__ int   g_off[N_NODES + 1];
static __device__ int   g_cur[N_NODES];
static __device__ int   g_csr[N_EDGES];
static __device__ float g_agg[(size_t)N_NODES * KDIM];   /* [N,512] fp32 */
static __device__ float g_sc[(size_t)N_NODES * 2];       /* samp, satt  */
static __device__ float g_WcT[(size_t)KDIM * NCOLS];     /* [512,384] transposed combined W */
static __device__ float g_G[(size_t)N_NODES * NCOLS];    /* GEMM result [N,384] */

/* ---------------- 1. init ------------------------------------------------ */
__global__ void init_cnt_k() {
    int i = blockIdx.x * blockDim.x + threadIdx.x;
    if (i < N_NODES) g_cnt[i] = 0;
}

/* ---------------- 2. degree count --------------------------------------- */
__global__ void count_k(const int* __restrict__ index) {
    int e = blockIdx.x * blockDim.x + threadIdx.x;
    if (e < N_EDGES) atomicAdd(&g_cnt[index[e]], 1);
}

/* ---------------- 3. exclusive prefix scan (single block) ---------------- */
__global__ void scan_k() {
    __shared__ int sh[1024];
    __shared__ int carry;
    if (threadIdx.x == 0) { carry = 0; g_off[0] = 0; }
    __syncthreads();
    for (int base = 0; base < N_NODES; base += 1024) {
        int i = base + threadIdx.x;
        int v = (i < N_NODES) ? g_cnt[i] : 0;
        sh[threadIdx.x] = v;
        __syncthreads();
        #pragma unroll
        for (int s = 1; s < 1024; s <<= 1) {
            int t = (threadIdx.x >= s) ? sh[threadIdx.x - s] : 0;
            __syncthreads();
            sh[threadIdx.x] += t;
            __syncthreads();
        }
        if (i < N_NODES) {
            int incl = carry + sh[threadIdx.x];
            g_off[i + 1] = incl;
            g_cur[i]     = incl - v;   /* exclusive offset = cursor start */
        }
        __syncthreads();
        if (threadIdx.x == 1023) carry += sh[1023];
        __syncthreads();
    }
}

/* ---------------- 4. scatter edge ids into CSR --------------------------- */
__global__ void scatter_k(const int* __restrict__ index) {
    int e = blockIdx.x * blockDim.x + threadIdx.x;
    if (e < N_EDGES) {
        int n = index[e];
        int p = atomicAdd(&g_cur[n], 1);
        g_csr[p] = e;
    }
}

/* ---------------- 5. gather + feature build (warp per node) -------------- */
__global__ void feat_k(const float* __restrict__ x) {
    int gwarp = (blockIdx.x * blockDim.x + threadIdx.x) >> 5;
    int lane  = threadIdx.x & 31;
    if (gwarp >= N_NODES) return;

    int beg = g_off[gwarp];
    int end = g_off[gwarp + 1];
    int deg = end - beg;

    float4 s1 = make_float4(0.f, 0.f, 0.f, 0.f);
    float4 s2 = make_float4(0.f, 0.f, 0.f, 0.f);
    float4 mn = make_float4( 3.4e38f,  3.4e38f,  3.4e38f,  3.4e38f);
    float4 mx = make_float4(-3.4e38f, -3.4e38f, -3.4e38f, -3.4e38f);

    const float4* x4 = (const float4*)x;
    for (int i = beg; i < end; i++) {
        int e = g_csr[i];
        float4 v = __ldg(&x4[(size_t)e * 32 + lane]);
        s1.x += v.x; s1.y += v.y; s1.z += v.z; s1.w += v.w;
        s2.x += v.x * v.x; s2.y += v.y * v.y; s2.z += v.z * v.z; s2.w += v.w * v.w;
        mn.x = fminf(mn.x, v.x); mn.y = fminf(mn.y, v.y);
        mn.z = fminf(mn.z, v.z); mn.w = fminf(mn.w, v.w);
        mx.x = fmaxf(mx.x, v.x); mx.y = fmaxf(mx.y, v.y);
        mx.z = fmaxf(mx.z, v.z); mx.w = fmaxf(mx.w, v.w);
    }

    float degc = (deg > 0) ? (float)deg : 1.0f;
    float inv  = 1.0f / degc;

    float4 mean, var, stdv;
    mean.x = s1.x * inv; mean.y = s1.y * inv; mean.z = s1.z * inv; mean.w = s1.w * inv;
    var.x = s2.x * inv - mean.x * mean.x;
    var.y = s2.y * inv - mean.y * mean.y;
    var.z = s2.z * inv - mean.z * mean.z;
    var.w = s2.w * inv - mean.w * mean.w;
    stdv.x = sqrtf(fmaxf(var.x, 0.f) + EPS_STD);
    stdv.y = sqrtf(fmaxf(var.y, 0.f) + EPS_STD);
    stdv.z = sqrtf(fmaxf(var.z, 0.f) + EPS_STD);
    stdv.w = sqrtf(fmaxf(var.w, 0.f) + EPS_STD);

    if (deg == 0) { /* torch_scatter empty-segment fill */
        mn = make_float4(0.f, 0.f, 0.f, 0.f);
        mx = make_float4(0.f, 0.f, 0.f, 0.f);
    }

    float* base = &g_agg[(size_t)gwarp * KDIM + lane * 4];
    *(float4*)(base + 0)   = mean;
    *(float4*)(base + 128) = mn;
    *(float4*)(base + 256) = mx;
    *(float4*)(base + 384) = stdv;

    if (lane == 0) {
        float ld = logf(degc + 1.0f);
        g_sc[2 * gwarp + 0] = ld / AVG_DEG_LOG;   /* amplification */
        g_sc[2 * gwarp + 1] = AVG_DEG_LOG / ld;   /* attenuation   */
    }
}

/* ---------------- 6. build WcT [512,384] from W [128,1536] ---------------
 * Wc[j,k] = W[(j&127), (j>>7)*512 + k]  ;  WcT[k,j] = Wc[j,k]
 * (column block 0 = W[:,0:512], 1 = W[:,512:1024], 2 = W[:,1024:1536]) */
__global__ void wtrans_k(const float* __restrict__ W) {
    int idx = blockIdx.x * blockDim.x + threadIdx.x;
    if (idx >= KDIM * NCOLS) return;
    int k = idx / NCOLS;
    int j = idx - k * NCOLS;
    g_WcT[idx] = W[(size_t)(j & 127) * 1536 + (j >> 7) * 512 + k];
}

/* ---------------- 7. GEMM: G[50000,384] = agg[50000,512] @ WcT ----------- */
/* BM=128 BN=128 BK=8, 256 threads, 8x8 per-thread register tile            */
__global__ __launch_bounds__(256) void gemm_k() {
    __shared__ float As[8][128];
    __shared__ float Bs[8][128];

    int tid  = threadIdx.x;
    int row0 = blockIdx.x * 128;
    int col0 = blockIdx.y * 128;

    int tr = (tid >> 4) * 8;       /* 0..120 step 8 */
    int tc = (tid & 15) * 8;       /* 0..120 step 8 */

    float acc[8][8];
    #pragma unroll
    for (int i = 0; i < 8; i++)
        #pragma unroll
        for (int j = 0; j < 8; j++) acc[i][j] = 0.f;

    int arow = row0 + (tid >> 1);
    int acol = (tid & 1) * 4;
    int brow = tid >> 5;           /* 0..7 */
    int bcol = (tid & 31) * 4;     /* 0..124 */

    for (int k0 = 0; k0 < KDIM; k0 += 8) {
        float4 av = make_float4(0.f, 0.f, 0.f, 0.f);
        if (arow < N_NODES)
            av = *(const float4*)&g_agg[(size_t)arow * KDIM + k0 + acol];
        As[acol + 0][tid >> 1] = av.x;
        As[acol + 1][tid >> 1] = av.y;
        As[acol + 2][tid >> 1] = av.z;
        As[acol + 3][tid >> 1] = av.w;

        float4 bv = *(const float4*)&g_WcT[(size_t)(k0 + brow) * NCOLS + col0 + bcol];
        *(float4*)&Bs[brow][bcol] = bv;

        __syncthreads();
        #pragma unroll
        for (int kk = 0; kk < 8; kk++) {
            float4 a0 = *(const float4*)&As[kk][tr];
            float4 a1 = *(const float4*)&As[kk][tr + 4];
            float4 b0 = *(const float4*)&Bs[kk][tc];
            float4 b1 = *(const float4*)&Bs[kk][tc + 4];
            float a[8] = {a0.x, a0.y, a0.z, a0.w, a1.x, a1.y, a1.z, a1.w};
            float b[8] = {b0.x, b0.y, b0.z, b0.w, b1.x, b1.y, b1.z, b1.w};
            #pragma unroll
            for (int i = 0; i < 8; i++)
                #pragma unroll
                for (int j = 0; j < 8; j++)
                    acc[i][j] = fmaf(a[i], b[j], acc[i][j]);
        }
        __syncthreads();
    }

    #pragma unroll
    for (int i = 0; i < 8; i++) {
        int r = row0 + tr + i;
        if (r < N_NODES) {
            float* dst = &g_G[(size_t)r * NCOLS + col0 + tc];
            *(float4*)(dst + 0) = make_float4(acc[i][0], acc[i][1], acc[i][2], acc[i][3]);
            *(float4*)(dst + 4) = make_float4(acc[i][4], acc[i][5], acc[i][6], acc[i][7]);
        }
    }
}

/* ---------------- 8. epilogue: combine 3 blocks with per-node scales ----- */
__global__ void epi_k(const float* __restrict__ b, float* __restrict__ out) {
    int idx = blockIdx.x * blockDim.x + threadIdx.x;   /* over N*32 float4 */
    if (idx >= N_NODES * 32) return;
    int n = idx >> 5;
    int c = (idx & 31) * 4;
    float samp = g_sc[2 * n + 0];
    float satt = g_sc[2 * n + 1];
    const float* g = &g_G[(size_t)n * NCOLS];
    float4 g1 = *(const float4*)(g + c);
    float4 g2 = *(const float4*)(g + 128 + c);
    float4 g3 = *(const float4*)(g + 256 + c);
    float4 bb = *(const float4*)(b + c);
    float4 o;
    o.x = g1.x + samp * g2.x + satt * g3.x + bb.x;
    o.y = g1.y + samp * g2.y + satt * g3.y + bb.y;
    o.z = g1.z + samp * g2.z + satt * g3.z + bb.z;
    o.w = g1.w + samp * g2.w + satt * g3.w + bb.w;
    *(float4*)&out[(size_t)n * DDIM + c] = o;
}

/* ---------------- launch -------------------------------------------------- */
extern "C" void kernel_launch(void* const* d_in, const int* in_sizes, int n_in,
                              void* d_out, int out_size) {
    const float* x     = (const float*)d_in[0];
    const int*   index = (const int*)d_in[1];
    const float* W     = (const float*)d_in[2];
    const float* b     = (const float*)d_in[3];
    float*       out   = (float*)d_out;
    (void)in_sizes; (void)n_in; (void)out_size;

    init_cnt_k<<<(N_NODES + 255) / 256, 256>>>();
    count_k<<<(N_EDGES + 255) / 256, 256>>>(index);
    scan_k<<<1, 1024>>>();
    scatter_k<<<(N_EDGES + 255) / 256, 256>>>(index);
    feat_k<<<(N_NODES * 32 + 255) / 256, 256>>>(x);
    wtrans_k<<<(KDIM * NCOLS + 255) / 256, 256>>>(W);
    dim3 ggrid((N_NODES + 127) / 128, NCOLS / 128);
    gemm_k<<<ggrid, 256>>>();
    epi_k<<<(N_NODES * 32 + 255) / 256, 256>>>(b, out);
}

// round 5
// speedup vs baseline: 1.6811x; 1.6811x over previous
#include <cuda_runtime.h>
#include <cuda_bf16.h>
#include <cstdint>
#include <math.h>

#define N_NODES 50000
#define N_EDGES 800000
#define DDIM    128
#define KDIM    512
#define NROWS_W 384           /* 3*128 combined output cols */

#define AVG_DEG_LOG 2.8332133440562162f  /* log(17) */
#define EPS_STD 1e-5f

/* ------------------- scratch (device globals) ---------------------------- */
static __device__ int   g_cnt[N_NODES];
static __device__ int   g_off[N_NODES + 1];
static __device__ int   g_cur[N_NODES];
static __device__ int   g_csr[N_EDGES];
static __device__ __nv_bfloat16 g_aggh[(size_t)N_NODES * KDIM];
static __device__ __nv_bfloat16 g_aggl[(size_t)N_NODES * KDIM];
static __device__ float g_sc[(size_t)N_NODES * 2];
static __device__ __nv_bfloat16 g_Wh[NROWS_W * KDIM];
static __device__ __nv_bfloat16 g_Wl[NROWS_W * KDIM];
static __device__ float g_G[(size_t)N_NODES * NROWS_W];   /* GEMM result [N,384] */

/* ------------------- 1-4: CSR build ------------------------------------- */
__global__ void init_cnt_k() {
    int i = blockIdx.x * blockDim.x + threadIdx.x;
    if (i < N_NODES) g_cnt[i] = 0;
}
__global__ void count_k(const int* __restrict__ index) {
    int e = blockIdx.x * blockDim.x + threadIdx.x;
    if (e < N_EDGES) atomicAdd(&g_cnt[index[e]], 1);
}
__global__ void scan_k() {
    __shared__ int sh[1024];
    __shared__ int carry;
    if (threadIdx.x == 0) { carry = 0; g_off[0] = 0; }
    __syncthreads();
    for (int base = 0; base < N_NODES; base += 1024) {
        int i = base + threadIdx.x;
        int v = (i < N_NODES) ? g_cnt[i] : 0;
        sh[threadIdx.x] = v;
        __syncthreads();
        #pragma unroll
        for (int s = 1; s < 1024; s <<= 1) {
            int t = (threadIdx.x >= s) ? sh[threadIdx.x - s] : 0;
            __syncthreads();
            sh[threadIdx.x] += t;
            __syncthreads();
        }
        if (i < N_NODES) {
            int incl = carry + sh[threadIdx.x];
            g_off[i + 1] = incl;
            g_cur[i] = incl - v;
        }
        __syncthreads();
        if (threadIdx.x == 1023) carry += sh[1023];
        __syncthreads();
    }
}
__global__ void scatter_k(const int* __restrict__ index) {
    int e = blockIdx.x * blockDim.x + threadIdx.x;
    if (e < N_EDGES) {
        int n = index[e];
        int p = atomicAdd(&g_cur[n], 1);
        g_csr[p] = e;
    }
}

/* ------------------- 5: features (bf16 hi/lo output) --------------------- */
__device__ __forceinline__ void split_w4(float4 v, __nv_bfloat16* hp, __nv_bfloat16* lp) {
    __nv_bfloat16 h0 = __float2bfloat16(v.x), h1 = __float2bfloat16(v.y);
    __nv_bfloat16 h2 = __float2bfloat16(v.z), h3 = __float2bfloat16(v.w);
    __nv_bfloat16 l0 = __float2bfloat16(v.x - __bfloat162float(h0));
    __nv_bfloat16 l1 = __float2bfloat16(v.y - __bfloat162float(h1));
    __nv_bfloat16 l2 = __float2bfloat16(v.z - __bfloat162float(h2));
    __nv_bfloat16 l3 = __float2bfloat16(v.w - __bfloat162float(h3));
    ((__nv_bfloat162*)hp)[0] = __halves2bfloat162(h0, h1);
    ((__nv_bfloat162*)hp)[1] = __halves2bfloat162(h2, h3);
    ((__nv_bfloat162*)lp)[0] = __halves2bfloat162(l0, l1);
    ((__nv_bfloat162*)lp)[1] = __halves2bfloat162(l2, l3);
}

__global__ void feat_k(const float* __restrict__ x) {
    int gwarp = (blockIdx.x * blockDim.x + threadIdx.x) >> 5;
    int lane  = threadIdx.x & 31;
    if (gwarp >= N_NODES) return;

    int beg = g_off[gwarp], end = g_off[gwarp + 1];
    int deg = end - beg;

    float4 s1 = make_float4(0.f, 0.f, 0.f, 0.f);
    float4 s2 = make_float4(0.f, 0.f, 0.f, 0.f);
    float4 mn = make_float4( 3.4e38f,  3.4e38f,  3.4e38f,  3.4e38f);
    float4 mx = make_float4(-3.4e38f, -3.4e38f, -3.4e38f, -3.4e38f);

    const float4* x4 = (const float4*)x;
    for (int i = beg; i < end; i++) {
        int e = g_csr[i];
        float4 v = __ldg(&x4[(size_t)e * 32 + lane]);
        s1.x += v.x; s1.y += v.y; s1.z += v.z; s1.w += v.w;
        s2.x += v.x*v.x; s2.y += v.y*v.y; s2.z += v.z*v.z; s2.w += v.w*v.w;
        mn.x = fminf(mn.x, v.x); mn.y = fminf(mn.y, v.y);
        mn.z = fminf(mn.z, v.z); mn.w = fminf(mn.w, v.w);
        mx.x = fmaxf(mx.x, v.x); mx.y = fmaxf(mx.y, v.y);
        mx.z = fmaxf(mx.z, v.z); mx.w = fmaxf(mx.w, v.w);
    }

    float degc = (deg > 0) ? (float)deg : 1.0f;
    float inv = 1.0f / degc;
    float4 mean, var, stdv;
    mean.x = s1.x*inv; mean.y = s1.y*inv; mean.z = s1.z*inv; mean.w = s1.w*inv;
    var.x = s2.x*inv - mean.x*mean.x;  var.y = s2.y*inv - mean.y*mean.y;
    var.z = s2.z*inv - mean.z*mean.z;  var.w = s2.w*inv - mean.w*mean.w;
    stdv.x = sqrtf(fmaxf(var.x, 0.f) + EPS_STD);
    stdv.y = sqrtf(fmaxf(var.y, 0.f) + EPS_STD);
    stdv.z = sqrtf(fmaxf(var.z, 0.f) + EPS_STD);
    stdv.w = sqrtf(fmaxf(var.w, 0.f) + EPS_STD);
    if (deg == 0) {
        mn = make_float4(0.f, 0.f, 0.f, 0.f);
        mx = make_float4(0.f, 0.f, 0.f, 0.f);
    }

    size_t base = (size_t)gwarp * KDIM + lane * 4;
    split_w4(mean, &g_aggh[base +   0], &g_aggl[base +   0]);
    split_w4(mn,   &g_aggh[base + 128], &g_aggl[base + 128]);
    split_w4(mx,   &g_aggh[base + 256], &g_aggl[base + 256]);
    split_w4(stdv, &g_aggh[base + 384], &g_aggl[base + 384]);

    if (lane == 0) {
        float ld = logf(degc + 1.0f);
        g_sc[2 * gwarp + 0] = ld / AVG_DEG_LOG;
        g_sc[2 * gwarp + 1] = AVG_DEG_LOG / ld;
    }
}

/* ------------------- 6: split W into bf16 hi/lo --------------------------
 * g_W{h,l}[j*512 + k] = split(W[(j&127)*1536 + (j>>7)*512 + k])            */
__global__ void wsplit_k(const float* __restrict__ W) {
    int idx = blockIdx.x * blockDim.x + threadIdx.x;
    if (idx >= NROWS_W * KDIM) return;
    int j = idx >> 9, k = idx & 511;
    float v = W[(size_t)(j & 127) * 1536 + (j >> 7) * 512 + k];
    __nv_bfloat16 h = __float2bfloat16(v);
    g_Wh[idx] = h;
    g_Wl[idx] = __float2bfloat16(v - __bfloat162float(h));
}

/* ------------------- 7: HMMA GEMM (mma.sync bf16, sm_80+ path) -----------
 * G[50000,384] = [Ah|Ah|Al] (K=1536) x [Bh;Bl;Bh]
 * BM=128 BN=128 BK=64, 256 threads, warp grid 4x2, warp tile 32x64.
 */
#define SW128(o) ((o) ^ (((o) >> 3) & 0x70))

__device__ __forceinline__ void ldm_x4(uint32_t* r, uint32_t addr) {
    asm volatile("ldmatrix.sync.aligned.m8n8.x4.shared.b16 {%0,%1,%2,%3}, [%4];"
                 : "=r"(r[0]), "=r"(r[1]), "=r"(r[2]), "=r"(r[3]) : "r"(addr));
}
__device__ __forceinline__ void mma16816(float* c, const uint32_t* a,
                                         uint32_t b0, uint32_t b1) {
    asm volatile("mma.sync.aligned.m16n8k16.row.col.f32.bf16.bf16.f32 "
                 "{%0,%1,%2,%3},{%4,%5,%6,%7},{%8,%9},{%0,%1,%2,%3};"
                 : "+f"(c[0]), "+f"(c[1]), "+f"(c[2]), "+f"(c[3])
                 : "r"(a[0]), "r"(a[1]), "r"(a[2]), "r"(a[3]), "r"(b0), "r"(b1));
}
__device__ __forceinline__ void cp16(uint32_t daddr, const void* g, int pred) {
    asm volatile("cp.async.ca.shared.global [%0], [%1], 16, %2;"
                 :: "r"(daddr), "l"(g), "r"(pred ? 16 : 0) : "memory");
}
#define CP_COMMIT() asm volatile("cp.async.commit_group;" ::: "memory")
#define CP_WAIT0()  asm volatile("cp.async.wait_group 0;" ::: "memory")

#define NKITER 24          /* K_eff=1536 / 64 */
#define TILE_BYTES 16384   /* 128 rows x 128B */
#define GEMM_SMEM  65536   /* 2 stages x (A + B) */

__device__ __forceinline__ void load_stage(char* smem, int buf, int iter,
                                           int row0, int by, int tid) {
    int phase = iter >> 3;                 /* 0: Ah*Bh, 1: Ah*Bl, 2: Al*Bh */
    int k0 = (iter & 7) * 64;              /* element offset within 512 */
    const __nv_bfloat16* Aarr = (phase == 2) ? g_aggl : g_aggh;
    const __nv_bfloat16* Barr = (phase == 1) ? g_Wl : g_Wh;
    uint32_t sA = 0, sB = 0;
    asm("{ .reg .u64 t; cvta.to.shared.u64 t, %1; cvt.u32.u64 %0, t; }"
        : "=r"(sA) : "l"(smem + buf * 2 * TILE_BYTES));
    sB = sA + TILE_BYTES;

    #pragma unroll
    for (int j = 0; j < 4; j++) {          /* A: 1024 16B chunks */
        int idx = j * 256 + tid;
        int row = idx >> 3, c = idx & 7;
        int gr = row0 + row;
        uint32_t o = row * 128 + c * 16;
        cp16(sA + SW128(o), Aarr + (size_t)gr * KDIM + k0 + c * 8, gr < N_NODES);
    }
    #pragma unroll
    for (int j = 0; j < 4; j++) {          /* B: 1024 16B chunks */
        int idx = j * 256 + tid;
        int row = idx >> 3, c = idx & 7;
        uint32_t o = row * 128 + c * 16;
        cp16(sB + SW128(o), Barr + (size_t)(by * 128 + row) * KDIM + k0 + c * 8, 1);
    }
}

__global__ void __launch_bounds__(256, 1) gemm_mma_k() {
    extern __shared__ char smem[];
    int tid  = threadIdx.x;
    int warp = tid >> 5, lane = tid & 31;
    int wm = warp >> 1, wn = warp & 1;     /* 4 x 2 warp grid */
    int row0 = blockIdx.x * 128;
    int by   = blockIdx.y;

    float acc[2][8][4];
    #pragma unroll
    for (int i = 0; i < 2; i++)
        #pragma unroll
        for (int j = 0; j < 8; j++)
            #pragma unroll
            for (int k = 0; k < 4; k++) acc[i][j][k] = 0.f;

    load_stage(smem, 0, 0, row0, by, tid);
    CP_COMMIT();

    for (int it = 0; it < NKITER; it++) {
        CP_WAIT0();
        __syncthreads();
        if (it + 1 < NKITER) {
            load_stage(smem, (it + 1) & 1, it + 1, row0, by, tid);
            CP_COMMIT();
        }
        uint32_t sA = 0;
        asm("{ .reg .u64 t; cvta.to.shared.u64 t, %1; cvt.u32.u64 %0, t; }"
            : "=r"(sA) : "l"(smem + (it & 1) * 2 * TILE_BYTES));
        uint32_t sB = sA + TILE_BYTES;

        #pragma unroll
        for (int kt = 0; kt < 4; kt++) {   /* 4 k16 steps */
            uint32_t af[2][4];
            #pragma unroll
            for (int mt = 0; mt < 2; mt++) {
                int r = wm * 32 + mt * 16 + (lane & 15);
                uint32_t o = r * 128 + kt * 32 + ((lane >> 4) * 16);
                ldm_x4(af[mt], sA + SW128(o));
            }
            uint32_t bfr[4][4];
            #pragma unroll
            for (int nt4 = 0; nt4 < 4; nt4++) {
                int n = wn * 64 + nt4 * 16 + (lane & 15);
                uint32_t o = n * 128 + kt * 32 + ((lane >> 4) * 16);
                ldm_x4(bfr[nt4], sB + SW128(o));
            }
            #pragma unroll
            for (int mt = 0; mt < 2; mt++)
                #pragma unroll
                for (int nt = 0; nt < 8; nt++) {
                    int n4 = nt >> 1, hi = nt & 1;
                    mma16816(acc[mt][nt], af[mt], bfr[n4][hi], bfr[n4][hi + 2]);
                }
        }
        __syncthreads();
    }

    /* epilogue: write accumulators to g_G [N, 384] */
    #pragma unroll
    for (int mt = 0; mt < 2; mt++)
        #pragma unroll
        for (int nt = 0; nt < 8; nt++) {
            int r = row0 + wm * 32 + mt * 16 + (lane >> 2);
            int c = by * 128 + wn * 64 + nt * 8 + (lane & 3) * 2;
            if (r < N_NODES)
                *(float2*)&g_G[(size_t)r * NROWS_W + c] =
                    make_float2(acc[mt][nt][0], acc[mt][nt][1]);
            if (r + 8 < N_NODES)
                *(float2*)&g_G[(size_t)(r + 8) * NROWS_W + c] =
                    make_float2(acc[mt][nt][2], acc[mt][nt][3]);
        }
}

/* ------------------- 8: epilogue combine --------------------------------- */
__global__ void epi_k(const float* __restrict__ b, float* __restrict__ out) {
    int idx = blockIdx.x * blockDim.x + threadIdx.x;
    if (idx >= N_NODES * 32) return;
    int n = idx >> 5;
    int c = (idx & 31) * 4;
    float samp = g_sc[2 * n + 0];
    float satt = g_sc[2 * n + 1];
    const float* g = &g_G[(size_t)n * NROWS_W];
    float4 g1 = *(const float4*)(g + c);
    float4 g2 = *(const float4*)(g + 128 + c);
    float4 g3 = *(const float4*)(g + 256 + c);
    float4 bb = *(const float4*)(b + c);
    float4 o;
    o.x = g1.x + samp * g2.x + satt * g3.x + bb.x;
    o.y = g1.y + samp * g2.y + satt * g3.y + bb.y;
    o.z = g1.z + samp * g2.z + satt * g3.z + bb.z;
    o.w = g1.w + samp * g2.w + satt * g3.w + bb.w;
    *(float4*)&out[(size_t)n * DDIM + c] = o;
}

/* ------------------- launch ---------------------------------------------- */
extern "C" void kernel_launch(void* const* d_in, const int* in_sizes, int n_in,
                              void* d_out, int out_size) {
    const float* x     = (const float*)d_in[0];
    const int*   index = (const int*)d_in[1];
    const float* W     = (const float*)d_in[2];
    const float* b     = (const float*)d_in[3];
    float*       out   = (float*)d_out;
    (void)in_sizes; (void)n_in; (void)out_size;

    cudaFuncSetAttribute(gemm_mma_k, cudaFuncAttributeMaxDynamicSharedMemorySize,
                         GEMM_SMEM);

    init_cnt_k<<<(N_NODES + 255) / 256, 256>>>();
    count_k<<<(N_EDGES + 255) / 256, 256>>>(index);
    scan_k<<<1, 1024>>>();
    scatter_k<<<(N_EDGES + 255) / 256, 256>>>(index);
    feat_k<<<(N_NODES * 32 + 255) / 256, 256>>>(x);
    wsplit_k<<<(NROWS_W * KDIM + 255) / 256, 256>>>(W);
    dim3 ggrid((N_NODES + 127) / 128, 3);
    gemm_mma_k<<<ggrid, 256, GEMM_SMEM>>>();
    epi_k<<<(N_NODES * 32 + 255) / 256, 256>>>(b, out);
}

// round 6
// speedup vs baseline: 1.9175x; 1.1406x over previous
#include <cuda_runtime.h>
#include <cuda_bf16.h>
#include <cstdint>
#include <math.h>

#define N_NODES 50000
#define N_EDGES 800000
#define DDIM    128
#define KDIM    512
#define NROWS_W 384           /* 3*128 combined output cols */

#define AVG_DEG_LOG 2.8332133440562162f  /* log(17) */
#define EPS_STD 1e-5f

#define SCAN_BLK  1024
#define SCAN_NBLK ((N_NODES + SCAN_BLK - 1) / SCAN_BLK)   /* 49 */

/* ------------------- scratch (device globals) ---------------------------- */
static __device__ int   g_cnt[N_NODES];            /* zero-init; feat_k re-zeroes */
static __device__ int   g_off[N_NODES + 1];        /* g_off[0] stays 0 forever */
static __device__ int   g_cur[N_NODES];
static __device__ int   g_csr[N_EDGES];
static __device__ int   g_bsum[64];
static __device__ int   g_boff[64];
static __device__ __nv_bfloat16 g_aggh[(size_t)N_NODES * KDIM];
static __device__ __nv_bfloat16 g_aggl[(size_t)N_NODES * KDIM];
static __device__ float g_sc[(size_t)N_NODES * 2];
static __device__ __nv_bfloat16 g_Wh[NROWS_W * KDIM];
static __device__ __nv_bfloat16 g_Wl[NROWS_W * KDIM];

/* ------------------- 1: degree count ------------------------------------- */
__global__ void count_k(const int* __restrict__ index) {
    int e = blockIdx.x * blockDim.x + threadIdx.x;
    if (e < N_EDGES) atomicAdd(&g_cnt[index[e]], 1);
}

/* ------------------- 2a: per-block inclusive scan ------------------------ */
__global__ void scanA_k() {
    __shared__ int sh[32];
    int i    = blockIdx.x * SCAN_BLK + threadIdx.x;
    int lane = threadIdx.x & 31, wid = threadIdx.x >> 5;
    int v = (i < N_NODES) ? g_cnt[i] : 0;
    int incl = v;
    #pragma unroll
    for (int s = 1; s < 32; s <<= 1) {
        int t = __shfl_up_sync(0xFFFFFFFFu, incl, s);
        if (lane >= s) incl += t;
    }
    if (lane == 31) sh[wid] = incl;
    __syncthreads();
    if (wid == 0) {
        int x = sh[lane];
        #pragma unroll
        for (int s = 1; s < 32; s <<= 1) {
            int t = __shfl_up_sync(0xFFFFFFFFu, x, s);
            if (lane >= s) x += t;
        }
        sh[lane] = x;
    }
    __syncthreads();
    if (wid > 0) incl += sh[wid - 1];
    if (i < N_NODES) {
        g_off[i + 1] = incl;
        g_cur[i]     = incl - v;
    }
    if (threadIdx.x == SCAN_BLK - 1) g_bsum[blockIdx.x] = incl;
}

/* ------------------- 2b: scan block sums (1 warp) ------------------------ */
__global__ void scanB_k() {
    int lane = threadIdx.x;
    int carry = 0;
    for (int base = 0; base < SCAN_NBLK; base += 32) {
        int v = (base + lane < SCAN_NBLK) ? g_bsum[base + lane] : 0;
        int incl = v;
        #pragma unroll
        for (int s = 1; s < 32; s <<= 1) {
            int t = __shfl_up_sync(0xFFFFFFFFu, incl, s);
            if (lane >= s) incl += t;
        }
        if (base + lane < SCAN_NBLK) g_boff[base + lane] = carry + incl - v;
        carry += __shfl_sync(0xFFFFFFFFu, incl, 31);
    }
}

/* ------------------- 2c: add back block offsets -------------------------- */
__global__ void scanC_k() {
    int i = blockIdx.x * SCAN_BLK + threadIdx.x;
    if (i < N_NODES) {
        int off = g_boff[blockIdx.x];
        g_off[i + 1] += off;
        g_cur[i]     += off;
    }
}

/* ------------------- 3: scatter edge ids into CSR ------------------------ */
__global__ void scatter_k(const int* __restrict__ index) {
    int e = blockIdx.x * blockDim.x + threadIdx.x;
    if (e < N_EDGES) {
        int n = index[e];
        int p = atomicAdd(&g_cur[n], 1);
        g_csr[p] = e;
    }
}

/* ------------------- 4: features (bf16 hi/lo output) --------------------- */
__device__ __forceinline__ void split_w4(float4 v, __nv_bfloat16* hp, __nv_bfloat16* lp) {
    __nv_bfloat16 h0 = __float2bfloat16(v.x), h1 = __float2bfloat16(v.y);
    __nv_bfloat16 h2 = __float2bfloat16(v.z), h3 = __float2bfloat16(v.w);
    __nv_bfloat16 l0 = __float2bfloat16(v.x - __bfloat162float(h0));
    __nv_bfloat16 l1 = __float2bfloat16(v.y - __bfloat162float(h1));
    __nv_bfloat16 l2 = __float2bfloat16(v.z - __bfloat162float(h2));
    __nv_bfloat16 l3 = __float2bfloat16(v.w - __bfloat162float(h3));
    ((__nv_bfloat162*)hp)[0] = __halves2bfloat162(h0, h1);
    ((__nv_bfloat162*)hp)[1] = __halves2bfloat162(h2, h3);
    ((__nv_bfloat162*)lp)[0] = __halves2bfloat162(l0, l1);
    ((__nv_bfloat162*)lp)[1] = __halves2bfloat162(l2, l3);
}

__global__ void feat_k(const float* __restrict__ x) {
    int gwarp = (blockIdx.x * blockDim.x + threadIdx.x) >> 5;
    int lane  = threadIdx.x & 31;
    if (gwarp >= N_NODES) return;

    int beg = g_off[gwarp], end = g_off[gwarp + 1];
    int deg = end - beg;

    float4 s1 = make_float4(0.f, 0.f, 0.f, 0.f);
    float4 s2 = make_float4(0.f, 0.f, 0.f, 0.f);
    float4 mn = make_float4( 3.4e38f,  3.4e38f,  3.4e38f,  3.4e38f);
    float4 mx = make_float4(-3.4e38f, -3.4e38f, -3.4e38f, -3.4e38f);

    const float4* x4 = (const float4*)x;
    for (int i = beg; i < end; i++) {
        int e = g_csr[i];
        float4 v = __ldg(&x4[(size_t)e * 32 + lane]);
        s1.x += v.x; s1.y += v.y; s1.z += v.z; s1.w += v.w;
        s2.x += v.x*v.x; s2.y += v.y*v.y; s2.z += v.z*v.z; s2.w += v.w*v.w;
        mn.x = fminf(mn.x, v.x); mn.y = fminf(mn.y, v.y);
        mn.z = fminf(mn.z, v.z); mn.w = fminf(mn.w, v.w);
        mx.x = fmaxf(mx.x, v.x); mx.y = fmaxf(mx.y, v.y);
        mx.z = fmaxf(mx.z, v.z); mx.w = fmaxf(mx.w, v.w);
    }

    float degc = (deg > 0) ? (float)deg : 1.0f;
    float inv = 1.0f / degc;
    float4 mean, var, stdv;
    mean.x = s1.x*inv; mean.y = s1.y*inv; mean.z = s1.z*inv; mean.w = s1.w*inv;
    var.x = s2.x*inv - mean.x*mean.x;  var.y = s2.y*inv - mean.y*mean.y;
    var.z = s2.z*inv - mean.z*mean.z;  var.w = s2.w*inv - mean.w*mean.w;
    stdv.x = sqrtf(fmaxf(var.x, 0.f) + EPS_STD);
    stdv.y = sqrtf(fmaxf(var.y, 0.f) + EPS_STD);
    stdv.z = sqrtf(fmaxf(var.z, 0.f) + EPS_STD);
    stdv.w = sqrtf(fmaxf(var.w, 0.f) + EPS_STD);
    if (deg == 0) {
        mn = make_float4(0.f, 0.f, 0.f, 0.f);
        mx = make_float4(0.f, 0.f, 0.f, 0.f);
    }

    size_t base = (size_t)gwarp * KDIM + lane * 4;
    split_w4(mean, &g_aggh[base +   0], &g_aggl[base +   0]);
    split_w4(mn,   &g_aggh[base + 128], &g_aggl[base + 128]);
    split_w4(mx,   &g_aggh[base + 256], &g_aggl[base + 256]);
    split_w4(stdv, &g_aggh[base + 384], &g_aggl[base + 384]);

    if (lane == 0) {
        float ld = logf(degc + 1.0f);
        g_sc[2 * gwarp + 0] = ld / AVG_DEG_LOG;
        g_sc[2 * gwarp + 1] = AVG_DEG_LOG / ld;
        g_cnt[gwarp] = 0;             /* reset for next graph replay */
    }
}

/* ------------------- 5: split W into bf16 hi/lo -------------------------- */
__global__ void wsplit_k(const float* __restrict__ W) {
    int idx = blockIdx.x * blockDim.x + threadIdx.x;
    if (idx >= NROWS_W * KDIM) return;
    int j = idx >> 9, k = idx & 511;
    float v = W[(size_t)(j & 127) * 1536 + (j >> 7) * 512 + k];
    __nv_bfloat16 h = __float2bfloat16(v);
    g_Wh[idx] = h;
    g_Wl[idx] = __float2bfloat16(v - __bfloat162float(h));
}

/* ------------------- 6: HMMA GEMM, fused epilogue ------------------------
 * For each CTA (128 rows): 72 flattened K-iters = 3 nb-blocks x (3 hi/lo
 * phases x 8 K-chunks).  After each nb-block, fold acc into out_acc with
 * per-row scale {1, samp, satt}.  3-stage cp.async pipeline.
 */
#define SW128(o) ((o) ^ (((o) >> 3) & 0x70))

__device__ __forceinline__ void ldm_x4(uint32_t* r, uint32_t addr) {
    asm volatile("ldmatrix.sync.aligned.m8n8.x4.shared.b16 {%0,%1,%2,%3}, [%4];"
                 : "=r"(r[0]), "=r"(r[1]), "=r"(r[2]), "=r"(r[3]) : "r"(addr));
}
__device__ __forceinline__ void mma16816(float* c, const uint32_t* a,
                                         uint32_t b0, uint32_t b1) {
    asm volatile("mma.sync.aligned.m16n8k16.row.col.f32.bf16.bf16.f32 "
                 "{%0,%1,%2,%3},{%4,%5,%6,%7},{%8,%9},{%0,%1,%2,%3};"
                 : "+f"(c[0]), "+f"(c[1]), "+f"(c[2]), "+f"(c[3])
                 : "r"(a[0]), "r"(a[1]), "r"(a[2]), "r"(a[3]), "r"(b0), "r"(b1));
}
__device__ __forceinline__ void cp16(uint32_t daddr, const void* g, int pred) {
    asm volatile("cp.async.ca.shared.global [%0], [%1], 16, %2;"
                 :: "r"(daddr), "l"(g), "r"(pred ? 16 : 0) : "memory");
}
#define CP_COMMIT() asm volatile("cp.async.commit_group;" ::: "memory")
#define CP_WAIT1()  asm volatile("cp.async.wait_group 1;" ::: "memory")

#define TOT_ITERS  72          /* 3 nb * 3 phase * 8 chunks */
#define TILE_BYTES 16384       /* 128 rows x 128B */
#define STAGE_BYTES 32768      /* A + B */
#define GEMM_SMEM  98304       /* 3 stages */

__device__ __forceinline__ void load_stage(char* smem, int t, int row0, int tid) {
    if (t >= TOT_ITERS) return;
    int nb    = t / 24;
    int r     = t - nb * 24;
    int phase = r >> 3;
    int k0    = (r & 7) * 64;
    const __nv_bfloat16* Aarr = (phase == 2) ? g_aggl : g_aggh;
    const __nv_bfloat16* Barr = (phase == 1) ? g_Wl : g_Wh;
    uint32_t sA = 0;
    asm("{ .reg .u64 t; cvta.to.shared.u64 t, %1; cvt.u32.u64 %0, t; }"
        : "=r"(sA) : "l"(smem + (t % 3) * STAGE_BYTES));
    uint32_t sB = sA + TILE_BYTES;

    #pragma unroll
    for (int j = 0; j < 4; j++) {
        int idx = j * 256 + tid;
        int row = idx >> 3, c = idx & 7;
        int gr = row0 + row;
        uint32_t o = row * 128 + c * 16;
        cp16(sA + SW128(o), Aarr + (size_t)gr * KDIM + k0 + c * 8, gr < N_NODES);
    }
    #pragma unroll
    for (int j = 0; j < 4; j++) {
        int idx = j * 256 + tid;
        int row = idx >> 3, c = idx & 7;
        uint32_t o = row * 128 + c * 16;
        cp16(sB + SW128(o), Barr + (size_t)(nb * 128 + row) * KDIM + k0 + c * 8, 1);
    }
}

__global__ void __launch_bounds__(256, 1) gemm_mma_k(const float* __restrict__ bias,
                                                     float* __restrict__ out) {
    extern __shared__ char smem[];
    int tid  = threadIdx.x;
    int warp = tid >> 5, lane = tid & 31;
    int wm = warp >> 1, wn = warp & 1;     /* 4 x 2 warp grid */
    int row0 = blockIdx.x * 128;

    /* per-thread row scale factors: rows r(mt,hi) = wm*32 + mt*16 + hi*8 + lane>>2 */
    float samp_r[2][2], satt_r[2][2];
    #pragma unroll
    for (int mt = 0; mt < 2; mt++)
        #pragma unroll
        for (int hi = 0; hi < 2; hi++) {
            int r = row0 + wm * 32 + mt * 16 + hi * 8 + (lane >> 2);
            samp_r[mt][hi] = (r < N_NODES) ? g_sc[2 * r] : 0.f;
            satt_r[mt][hi] = (r < N_NODES) ? g_sc[2 * r + 1] : 0.f;
        }

    float acc[2][8][4], oacc[2][8][4];
    #pragma unroll
    for (int i = 0; i < 2; i++)
        #pragma unroll
        for (int j = 0; j < 8; j++)
            #pragma unroll
            for (int k = 0; k < 4; k++) { acc[i][j][k] = 0.f; oacc[i][j][k] = 0.f; }

    load_stage(smem, 0, row0, tid);
    CP_COMMIT();
    load_stage(smem, 1, row0, tid);
    CP_COMMIT();

    for (int t = 0; t < TOT_ITERS; t++) {
        CP_WAIT1();
        __syncthreads();
        load_stage(smem, t + 2, row0, tid);
        CP_COMMIT();

        uint32_t sA = 0;
        asm("{ .reg .u64 u; cvta.to.shared.u64 u, %1; cvt.u32.u64 %0, u; }"
            : "=r"(sA) : "l"(smem + (t % 3) * STAGE_BYTES));
        uint32_t sB = sA + TILE_BYTES;

        #pragma unroll
        for (int kt = 0; kt < 4; kt++) {
            uint32_t af[2][4];
            #pragma unroll
            for (int mt = 0; mt < 2; mt++) {
                int r = wm * 32 + mt * 16 + (lane & 15);
                uint32_t o = r * 128 + kt * 32 + ((lane >> 4) * 16);
                ldm_x4(af[mt], sA + SW128(o));
            }
            uint32_t bfr[4][4];
            #pragma unroll
            for (int nt4 = 0; nt4 < 4; nt4++) {
                int n = wn * 64 + nt4 * 16 + (lane & 15);
                uint32_t o = n * 128 + kt * 32 + ((lane >> 4) * 16);
                ldm_x4(bfr[nt4], sB + SW128(o));
            }
            #pragma unroll
            for (int mt = 0; mt < 2; mt++)
                #pragma unroll
                for (int nt = 0; nt < 8; nt++) {
                    int n4 = nt >> 1, hi = nt & 1;
                    mma16816(acc[mt][nt], af[mt], bfr[n4][hi], bfr[n4][hi + 2]);
                }
        }

        if ((t & 7) == 7 && (t % 24) == 23) {   /* end of an nb block */
            int nb = t / 24;
            #pragma unroll
            for (int mt = 0; mt < 2; mt++)
                #pragma unroll
                for (int nt = 0; nt < 8; nt++) {
                    float s0, s1;
                    if (nb == 0)      { s0 = 1.f;            s1 = 1.f; }
                    else if (nb == 1) { s0 = samp_r[mt][0];  s1 = samp_r[mt][1]; }
                    else              { s0 = satt_r[mt][0];  s1 = satt_r[mt][1]; }
                    oacc[mt][nt][0] += s0 * acc[mt][nt][0];
                    oacc[mt][nt][1] += s0 * acc[mt][nt][1];
                    oacc[mt][nt][2] += s1 * acc[mt][nt][2];
                    oacc[mt][nt][3] += s1 * acc[mt][nt][3];
                    acc[mt][nt][0] = 0.f; acc[mt][nt][1] = 0.f;
                    acc[mt][nt][2] = 0.f; acc[mt][nt][3] = 0.f;
                }
        }
        __syncthreads();
    }

    /* write out + bias */
    #pragma unroll
    for (int mt = 0; mt < 2; mt++)
        #pragma unroll
        for (int nt = 0; nt < 8; nt++) {
            int r = row0 + wm * 32 + mt * 16 + (lane >> 2);
            int c = wn * 64 + nt * 8 + (lane & 3) * 2;
            float b0 = bias[c], b1 = bias[c + 1];
            if (r < N_NODES)
                *(float2*)&out[(size_t)r * DDIM + c] =
                    make_float2(oacc[mt][nt][0] + b0, oacc[mt][nt][1] + b1);
            if (r + 8 < N_NODES)
                *(float2*)&out[(size_t)(r + 8) * DDIM + c] =
                    make_float2(oacc[mt][nt][2] + b0, oacc[mt][nt][3] + b1);
        }
}

/* ------------------- launch ---------------------------------------------- */
extern "C" void kernel_launch(void* const* d_in, const int* in_sizes, int n_in,
                              void* d_out, int out_size) {
    const float* x     = (const float*)d_in[0];
    const int*   index = (const int*)d_in[1];
    const float* W     = (const float*)d_in[2];
    const float* b     = (const float*)d_in[3];
    float*       out   = (float*)d_out;
    (void)in_sizes; (void)n_in; (void)out_size;

    cudaFuncSetAttribute(gemm_mma_k, cudaFuncAttributeMaxDynamicSharedMemorySize,
                         GEMM_SMEM);

    wsplit_k<<<(NROWS_W * KDIM + 255) / 256, 256>>>(W);
    count_k<<<(N_EDGES + 255) / 256, 256>>>(index);
    scanA_k<<<SCAN_NBLK, SCAN_BLK>>>();
    scanB_k<<<1, 32>>>();
    scanC_k<<<SCAN_NBLK, SCAN_BLK>>>();
    scatter_k<<<(N_EDGES + 255) / 256, 256>>>(index);
    feat_k<<<(N_NODES * 32 + 255) / 256, 256>>>(x);
    gemm_mma_k<<<(N_NODES + 127) / 128, 256, GEMM_SMEM>>>(b, out);
}

// round 9
// speedup vs baseline: 1.9178x; 1.0002x over previous
#include <cuda_runtime.h>
#include <cuda_bf16.h>
#include <cstdint>
#include <math.h>

#define N_NODES 50000
#define N_EDGES 800000
#define DDIM    128
#define KDIM    512
#define NROWS_W 384           /* 3*128 combined output cols */

#define AVG_DEG_LOG 2.8332133440562162f  /* log(17) */
#define EPS_STD 1e-5f

#define SCAN_BLK  1024
#define SCAN_NBLK ((N_NODES + SCAN_BLK - 1) / SCAN_BLK)   /* 49 */

/* ------------------- scratch (device globals) ---------------------------- */
static __device__ int   g_cnt[N_NODES];            /* zero-init; feat_k re-zeroes */
static __device__ int   g_off[N_NODES + 1];        /* g_off[0] stays 0 forever */
static __device__ int   g_cur[N_NODES];
static __device__ int   g_csr[N_EDGES];
static __device__ int   g_bsum[64];
static __device__ int   g_boff[64];
static __device__ __nv_bfloat16 g_aggh[(size_t)N_NODES * KDIM];
static __device__ __nv_bfloat16 g_aggl[(size_t)N_NODES * KDIM];
static __device__ float g_sc[(size_t)N_NODES * 2];
static __device__ __nv_bfloat16 g_Wh[NROWS_W * KDIM];
static __device__ __nv_bfloat16 g_Wl[NROWS_W * KDIM];

/* ------------------- 1: degree count ------------------------------------- */
__global__ void count_k(const int* __restrict__ index) {
    int e = blockIdx.x * blockDim.x + threadIdx.x;
    if (e < N_EDGES) atomicAdd(&g_cnt[index[e]], 1);
}

/* ------------------- 2a: per-block inclusive scan ------------------------ */
__global__ void scanA_k() {
    __shared__ int sh[32];
    int i    = blockIdx.x * SCAN_BLK + threadIdx.x;
    int lane = threadIdx.x & 31, wid = threadIdx.x >> 5;
    int v = (i < N_NODES) ? g_cnt[i] : 0;
    int incl = v;
    #pragma unroll
    for (int s = 1; s < 32; s <<= 1) {
        int t = __shfl_up_sync(0xFFFFFFFFu, incl, s);
        if (lane >= s) incl += t;
    }
    if (lane == 31) sh[wid] = incl;
    __syncthreads();
    if (wid == 0) {
        int x = sh[lane];
        #pragma unroll
        for (int s = 1; s < 32; s <<= 1) {
            int t = __shfl_up_sync(0xFFFFFFFFu, x, s);
            if (lane >= s) x += t;
        }
        sh[lane] = x;
    }
    __syncthreads();
    if (wid > 0) incl += sh[wid - 1];
    if (i < N_NODES) {
        g_off[i + 1] = incl;
        g_cur[i]     = incl - v;
    }
    if (threadIdx.x == SCAN_BLK - 1) g_bsum[blockIdx.x] = incl;
}

/* ------------------- 2b: scan block sums (1 warp) ------------------------ */
__global__ void scanB_k() {
    int lane = threadIdx.x;
    int carry = 0;
    for (int base = 0; base < SCAN_NBLK; base += 32) {
        int v = (base + lane < SCAN_NBLK) ? g_bsum[base + lane] : 0;
        int incl = v;
        #pragma unroll
        for (int s = 1; s < 32; s <<= 1) {
            int t = __shfl_up_sync(0xFFFFFFFFu, incl, s);
            if (lane >= s) incl += t;
        }
        if (base + lane < SCAN_NBLK) g_boff[base + lane] = carry + incl - v;
        carry += __shfl_sync(0xFFFFFFFFu, incl, 31);
    }
}

/* ------------------- 2c: add back block offsets -------------------------- */
__global__ void scanC_k() {
    int i = blockIdx.x * SCAN_BLK + threadIdx.x;
    if (i < N_NODES) {
        int off = g_boff[blockIdx.x];
        g_off[i + 1] += off;
        g_cur[i]     += off;
    }
}

/* ------------------- 3: scatter edge ids into CSR ------------------------ */
__global__ void scatter_k(const int* __restrict__ index) {
    int e = blockIdx.x * blockDim.x + threadIdx.x;
    if (e < N_EDGES) {
        int n = index[e];
        int p = atomicAdd(&g_cur[n], 1);
        g_csr[p] = e;
    }
}

/* ------------------- 4: features (bf16 hi/lo output) --------------------- */
__device__ __forceinline__ void split_w4(float4 v, __nv_bfloat16* hp, __nv_bfloat16* lp) {
    __nv_bfloat16 h0 = __float2bfloat16(v.x), h1 = __float2bfloat16(v.y);
    __nv_bfloat16 h2 = __float2bfloat16(v.z), h3 = __float2bfloat16(v.w);
    __nv_bfloat16 l0 = __float2bfloat16(v.x - __bfloat162float(h0));
    __nv_bfloat16 l1 = __float2bfloat16(v.y - __bfloat162float(h1));
    __nv_bfloat16 l2 = __float2bfloat16(v.z - __bfloat162float(h2));
    __nv_bfloat16 l3 = __float2bfloat16(v.w - __bfloat162float(h3));
    ((__nv_bfloat162*)hp)[0] = __halves2bfloat162(h0, h1);
    ((__nv_bfloat162*)hp)[1] = __halves2bfloat162(h2, h3);
    ((__nv_bfloat162*)lp)[0] = __halves2bfloat162(l0, l1);
    ((__nv_bfloat162*)lp)[1] = __halves2bfloat162(l2, l3);
}

__global__ void feat_k(const float* __restrict__ x) {
    int gwarp = (blockIdx.x * blockDim.x + threadIdx.x) >> 5;
    int lane  = threadIdx.x & 31;
    if (gwarp >= N_NODES) return;

    int beg = g_off[gwarp], end = g_off[gwarp + 1];
    int deg = end - beg;

    float4 s1 = make_float4(0.f, 0.f, 0.f, 0.f);
    float4 s2 = make_float4(0.f, 0.f, 0.f, 0.f);
    float4 mn = make_float4( 3.4e38f,  3.4e38f,  3.4e38f,  3.4e38f);
    float4 mx = make_float4(-3.4e38f, -3.4e38f, -3.4e38f, -3.4e38f);

    const float4* x4 = (const float4*)x;
    for (int i = beg; i < end; i++) {
        int e = g_csr[i];
        float4 v = __ldg(&x4[(size_t)e * 32 + lane]);
        s1.x += v.x; s1.y += v.y; s1.z += v.z; s1.w += v.w;
        s2.x += v.x*v.x; s2.y += v.y*v.y; s2.z += v.z*v.z; s2.w += v.w*v.w;
        mn.x = fminf(mn.x, v.x); mn.y = fminf(mn.y, v.y);
        mn.z = fminf(mn.z, v.z); mn.w = fminf(mn.w, v.w);
        mx.x = fmaxf(mx.x, v.x); mx.y = fmaxf(mx.y, v.y);
        mx.z = fmaxf(mx.z, v.z); mx.w = fmaxf(mx.w, v.w);
    }

    float degc = (deg > 0) ? (float)deg : 1.0f;
    float inv = 1.0f / degc;
    float4 mean, var, stdv;
    mean.x = s1.x*inv; mean.y = s1.y*inv; mean.z = s1.z*inv; mean.w = s1.w*inv;
    var.x = s2.x*inv - mean.x*mean.x;  var.y = s2.y*inv - mean.y*mean.y;
    var.z = s2.z*inv - mean.z*mean.z;  var.w = s2.w*inv - mean.w*mean.w;
    stdv.x = sqrtf(fmaxf(var.x, 0.f) + EPS_STD);
    stdv.y = sqrtf(fmaxf(var.y, 0.f) + EPS_STD);
    stdv.z = sqrtf(fmaxf(var.z, 0.f) + EPS_STD);
    stdv.w = sqrtf(fmaxf(var.w, 0.f) + EPS_STD);
    if (deg == 0) {
        mn = make_float4(0.f, 0.f, 0.f, 0.f);
        mx = make_float4(0.f, 0.f, 0.f, 0.f);
    }

    size_t base = (size_t)gwarp * KDIM + lane * 4;
    split_w4(mean, &g_aggh[base +   0], &g_aggl[base +   0]);
    split_w4(mn,   &g_aggh[base + 128], &g_aggl[base + 128]);
    split_w4(mx,   &g_aggh[base + 256], &g_aggl[base + 256]);
    split_w4(stdv, &g_aggh[base + 384], &g_aggl[base + 384]);

    if (lane == 0) {
        float ld = logf(degc + 1.0f);
        g_sc[2 * gwarp + 0] = ld / AVG_DEG_LOG;
        g_sc[2 * gwarp + 1] = AVG_DEG_LOG / ld;
        g_cnt[gwarp] = 0;             /* reset for next graph replay */
    }
}

/* ------------------- 5: split W into bf16 hi/lo -------------------------- */
__global__ void wsplit_k(const float* __restrict__ W) {
    int idx = blockIdx.x * blockDim.x + threadIdx.x;
    if (idx >= NROWS_W * KDIM) return;
    int j = idx >> 9, k = idx & 511;
    float v = W[(size_t)(j & 127) * 1536 + (j >> 7) * 512 + k];
    __nv_bfloat16 h = __float2bfloat16(v);
    g_Wh[idx] = h;
    g_Wl[idx] = __float2bfloat16(v - __bfloat162float(h));
}

/* ------------------- 6: HMMA GEMM, all-operands-resident chunks ----------
 * 16 chunks of K=32.  Per chunk: stage holds Ah,Al (128x32) + Bh,Bl
 * (384x32).  Compute AhBh+AhBl+AlBh for each of 3 output blocks, fold into
 * oacc with per-row scale {1, samp, satt}.  3-stage cp.async pipeline.
 */
#define SW64(o) ((o) ^ (((o) >> 3) & 0x30))

__device__ __forceinline__ void ldm_x4(uint32_t* r, uint32_t addr) {
    asm volatile("ldmatrix.sync.aligned.m8n8.x4.shared.b16 {%0,%1,%2,%3}, [%4];"
                 : "=r"(r[0]), "=r"(r[1]), "=r"(r[2]), "=r"(r[3]) : "r"(addr));
}
__device__ __forceinline__ void mma16816(float* c, const uint32_t* a,
                                         uint32_t b0, uint32_t b1) {
    asm volatile("mma.sync.aligned.m16n8k16.row.col.f32.bf16.bf16.f32 "
                 "{%0,%1,%2,%3},{%4,%5,%6,%7},{%8,%9},{%0,%1,%2,%3};"
                 : "+f"(c[0]), "+f"(c[1]), "+f"(c[2]), "+f"(c[3])
                 : "r"(a[0]), "r"(a[1]), "r"(a[2]), "r"(a[3]), "r"(b0), "r"(b1));
}
__device__ __forceinline__ void cp16(uint32_t daddr, const void* g, int pred) {
    asm volatile("cp.async.ca.shared.global [%0], [%1], 16, %2;"
                 :: "r"(daddr), "l"(g), "r"(pred ? 16 : 0) : "memory");
}
#define CP_COMMIT() asm volatile("cp.async.commit_group;" ::: "memory")
#define CP_WAIT1()  asm volatile("cp.async.wait_group 1;" ::: "memory")

#define NCHUNK 16              /* K=512 / 32 */
#define SM_AH  0
#define SM_AL  8192
#define SM_BH  16384
#define SM_BL  40960
#define STAGE_BYTES 65536      /* Ah+Al+Bh+Bl */
#define GEMM_SMEM  196608      /* 3 stages */

__device__ __forceinline__ uint32_t smem_u32(const void* p) {
    uint32_t a;
    asm("{ .reg .u64 t; cvta.to.shared.u64 t, %1; cvt.u32.u64 %0, t; }" : "=r"(a) : "l"(p));
    return a;
}

__device__ __forceinline__ void load_stage(char* smem, int t, int row0, int tid) {
    if (t >= NCHUNK) return;
    int k0 = t * 32;
    uint32_t s0 = smem_u32(smem + (t % 3) * STAGE_BYTES);

    /* A hi/lo: 128 rows x 32 bf16 (64B rows), 512 segs each */
    #pragma unroll
    for (int j = 0; j < 2; j++) {
        int idx = j * 256 + tid;
        int row = idx >> 2, c = idx & 3;
        int gr = row0 + row;
        uint32_t o = row * 64 + c * 16;
        uint32_t sw = SW64(o);
        size_t gofs = (size_t)gr * KDIM + k0 + c * 8;
        cp16(s0 + SM_AH + sw, g_aggh + gofs, gr < N_NODES);
        cp16(s0 + SM_AL + sw, g_aggl + gofs, gr < N_NODES);
    }
    /* B hi/lo: 384 rows x 32 bf16, 1536 segs each */
    #pragma unroll
    for (int j = 0; j < 6; j++) {
        int idx = j * 256 + tid;
        int row = idx >> 2, c = idx & 3;
        uint32_t o = row * 64 + c * 16;
        uint32_t sw = SW64(o);
        size_t gofs = (size_t)row * KDIM + k0 + c * 8;
        cp16(s0 + SM_BH + sw, g_Wh + gofs, 1);
        cp16(s0 + SM_BL + sw, g_Wl + gofs, 1);
    }
}

__global__ void __launch_bounds__(256, 1) gemm_mma_k(const float* __restrict__ bias,
                                                     float* __restrict__ out) {
    extern __shared__ char smem[];
    int tid  = threadIdx.x;
    int warp = tid >> 5, lane = tid & 31;
    int wm = warp >> 1, wn = warp & 1;     /* 4 x 2 warp grid, warp tile 32x64 */
    int row0 = blockIdx.x * 128;

    /* per-thread row scale factors for fold */
    float samp_r[2][2], satt_r[2][2];
    #pragma unroll
    for (int mt = 0; mt < 2; mt++)
        #pragma unroll
        for (int hi = 0; hi < 2; hi++) {
            int r = row0 + wm * 32 + mt * 16 + hi * 8 + (lane >> 2);
            samp_r[mt][hi] = (r < N_NODES) ? g_sc[2 * r] : 0.f;
            satt_r[mt][hi] = (r < N_NODES) ? g_sc[2 * r + 1] : 0.f;
        }

    float acc[2][8][4], oacc[2][8][4];
    #pragma unroll
    for (int i = 0; i < 2; i++)
        #pragma unroll
        for (int j = 0; j < 8; j++)
            #pragma unroll
            for (int k = 0; k < 4; k++) { acc[i][j][k] = 0.f; oacc[i][j][k] = 0.f; }

    load_stage(smem, 0, row0, tid);
    CP_COMMIT();
    load_stage(smem, 1, row0, tid);
    CP_COMMIT();

    for (int t = 0; t < NCHUNK; t++) {
        CP_WAIT1();
        __syncthreads();
        load_stage(smem, t + 2, row0, tid);
        CP_COMMIT();

        uint32_t s0 = smem_u32(smem + (t % 3) * STAGE_BYTES);

        /* A fragments: both kt halves, hi and lo, resident for whole chunk */
        uint32_t afh[2][2][4], afl[2][2][4];
        #pragma unroll
        for (int kt = 0; kt < 2; kt++)
            #pragma unroll
            for (int mt = 0; mt < 2; mt++) {
                int r = wm * 32 + mt * 16 + (lane & 15);
                uint32_t o = r * 64 + kt * 32 + ((lane >> 4) * 16);
                uint32_t sw = SW64(o);
                ldm_x4(afh[kt][mt], s0 + SM_AH + sw);
                ldm_x4(afl[kt][mt], s0 + SM_AL + sw);
            }

        #pragma unroll
        for (int nb = 0; nb < 3; nb++) {
            #pragma unroll
            for (int kt = 0; kt < 2; kt++) {
                #pragma unroll
                for (int n4 = 0; n4 < 4; n4++) {
                    int n = nb * 128 + wn * 64 + n4 * 16 + (lane & 15);
                    uint32_t o = n * 64 + kt * 32 + ((lane >> 4) * 16);
                    uint32_t sw = SW64(o);
                    uint32_t bh[4], bl[4];
                    ldm_x4(bh, s0 + SM_BH + sw);
                    ldm_x4(bl, s0 + SM_BL + sw);
                    #pragma unroll
                    for (int mt = 0; mt < 2; mt++)
                        #pragma unroll
                        for (int hi = 0; hi < 2; hi++) {
                            int nt = n4 * 2 + hi;
                            mma16816(acc[mt][nt], afh[kt][mt], bh[hi], bh[hi + 2]);
                            mma16816(acc[mt][nt], afh[kt][mt], bl[hi], bl[hi + 2]);
                            mma16816(acc[mt][nt], afl[kt][mt], bh[hi], bh[hi + 2]);
                        }
                }
            }
            /* fold this output block into oacc, reset acc */
            #pragma unroll
            for (int mt = 0; mt < 2; mt++)
                #pragma unroll
                for (int nt = 0; nt < 8; nt++) {
                    float s0f, s1f;
                    if (nb == 0)      { s0f = 1.f;            s1f = 1.f; }
                    else if (nb == 1) { s0f = samp_r[mt][0];  s1f = samp_r[mt][1]; }
                    else              { s0f = satt_r[mt][0];  s1f = satt_r[mt][1]; }
                    oacc[mt][nt][0] += s0f * acc[mt][nt][0];
                    oacc[mt][nt][1] += s0f * acc[mt][nt][1];
                    oacc[mt][nt][2] += s1f * acc[mt][nt][2];
                    oacc[mt][nt][3] += s1f * acc[mt][nt][3];
                    acc[mt][nt][0] = 0.f; acc[mt][nt][1] = 0.f;
                    acc[mt][nt][2] = 0.f; acc[mt][nt][3] = 0.f;
                }
        }
    }

    /* write out + bias */
    #pragma unroll
    for (int mt = 0; mt < 2; mt++)
        #pragma unroll
        for (int nt = 0; nt < 8; nt++) {
            int r = row0 + wm * 32 + mt * 16 + (lane >> 2);
            int c = wn * 64 + nt * 8 + (lane & 3) * 2;
            float b0 = bias[c], b1 = bias[c + 1];
            if (r < N_NODES)
                *(float2*)&out[(size_t)r * DDIM + c] =
                    make_float2(oacc[mt][nt][0] + b0, oacc[mt][nt][1] + b1);
            if (r + 8 < N_NODES)
                *(float2*)&out[(size_t)(r + 8) * DDIM + c] =
                    make_float2(oacc[mt][nt][2] + b0, oacc[mt][nt][3] + b1);
        }
}

/* ------------------- launch ---------------------------------------------- */
extern "C" void kernel_launch(void* const* d_in, const int* in_sizes, int n_in,
                              void* d_out, int out_size) {
    const float* x     = (const float*)d_in[0];
    const int*   index = (const int*)d_in[1];
    const float* W     = (const float*)d_in[2];
    const float* b     = (const float*)d_in[3];
    float*       out   = (float*)d_out;
    (void)in_sizes; (void)n_in; (void)out_size;

    cudaFuncSetAttribute(gemm_mma_k, cudaFuncAttributeMaxDynamicSharedMemorySize,
                         GEMM_SMEM);

    wsplit_k<<<(NROWS_W * KDIM + 255) / 256, 256>>>(W);
    count_k<<<(N_EDGES + 255) / 256, 256>>>(index);
    scanA_k<<<SCAN_NBLK, SCAN_BLK>>>();
    scanB_k<<<1, 32>>>();
    scanC_k<<<SCAN_NBLK, SCAN_BLK>>>();
    scatter_k<<<(N_EDGES + 255) / 256, 256>>>(index);
    feat_k<<<(N_NODES * 32 + 255) / 256, 256>>>(x);
    gemm_mma_k<<<(N_NODES + 127) / 128, 256, GEMM_SMEM>>>(b, out);
}